// round 3
// baseline (speedup 1.0000x reference)
#include <cuda_runtime.h>

#define EPSF 1e-20f

constexpr int B = 8, C = 32, O = 32, H = 256, W = 256;
constexpr int HW = H * W;                       // 65536
constexpr long long NTOT = (long long)B * C * HW; // 16,777,216 elements per tensor

// Scratch (allocation-free rule: __device__ globals). 128 MiB.
__device__ float2 g_pq[B * C * HW];
__device__ float  g_cw[O * C];
__device__ float  g_invSsw, g_invScw;

__device__ __forceinline__ float softplusf(float x) {
    // matches jax.nn.softplus for the small-magnitude weights here
    return log1pf(expf(x));
}

// ---------------------------------------------------------------------------
// K0: softplus the tiny weight tensors, compute 1/sum(sw) and 1/sum(cw)
// ---------------------------------------------------------------------------
__global__ void k0_weights(const float* __restrict__ sw_raw,
                           const float* __restrict__ cw_raw) {
    __shared__ float red[256];
    int t = threadIdx.x;

    float s = 0.f;
    for (int i = t; i < C * 25; i += 256) s += softplusf(sw_raw[i]);
    red[t] = s; __syncthreads();
    for (int o = 128; o > 0; o >>= 1) { if (t < o) red[t] += red[t + o]; __syncthreads(); }
    if (t == 0) g_invSsw = 1.0f / red[0];
    __syncthreads();

    s = 0.f;
    for (int i = t; i < O * C; i += 256) {
        float v = softplusf(cw_raw[i]);
        g_cw[i] = v;
        s += v;
    }
    red[t] = s; __syncthreads();
    for (int o = 128; o > 0; o >>= 1) { if (t < o) red[t] += red[t + o]; __syncthreads(); }
    if (t == 0) g_invScw = 1.0f / red[0];
}

// ---------------------------------------------------------------------------
// K12: fused elementwise-prop + depthwise 5x5 conv (pad=2).
// One block = one (b, c, 32x32 tile). Phase A computes the per-pixel prop
// values for the 36x36 halo tile into smem; Phase B does the conv with
// 4 vertical outputs per thread (8 smem rows / 4 outputs reuse).
// Writes interleaved (p, q) = (cgx_s*gx_s, cgx_s) as float2.
// ---------------------------------------------------------------------------
__global__ __launch_bounds__(256) void k12_prop_dwconv(
    const float* __restrict__ d, const float* __restrict__ cd,
    const float* __restrict__ gx, const float* __restrict__ cgx,
    const float* __restrict__ w_prop, const float* __restrict__ sw_raw) {

    __shared__ float sP[36 * 37];
    __shared__ float sQ[36 * 37];
    __shared__ float sw_s[25];
    __shared__ float s_inv;

    const int tid = threadIdx.x;
    const int b = blockIdx.z, c = blockIdx.y;
    const int h0 = (blockIdx.x >> 3) * 32;
    const int w0 = (blockIdx.x & 7) * 32;

    const float wp = softplusf(w_prop[c]);
    if (tid < 25) sw_s[tid] = softplusf(sw_raw[c * 25 + tid]);
    if (tid == 25) s_inv = g_invSsw;

    const size_t plane = ((size_t)b * C + c) * HW;

    // Phase A: halo tile (36x36) of per-pixel prop values
    for (int idx = tid; idx < 36 * 36; idx += 256) {
        int hh = idx / 36, ww = idx - hh * 36;
        int gh = h0 + hh - 2, gw = w0 + ww - 2;
        float p = 0.f, q = 0.f;
        if ((unsigned)gh < (unsigned)H && (unsigned)gw < (unsigned)W) {
            size_t g = plane + (size_t)gh * W + gw;
            float dv = d[g], cdv = cd[g], gv = gx[g], cgv = cgx[g];
            // reference slicing: *_left keeps value unless last col, *_right unless first col
            bool nl = (gw < W - 1), nf = (gw > 0);
            float dl = nl ? dv : 0.f, cl = nl ? cdv : 0.f;
            float dr = nf ? dv : 0.f, cr = nf ? cdv : 0.f;
            float cds = cl * cr;
            float height = (cl * dl + cr * dr) / (cl + cr + EPSF);
            float gds = (dr - dl) * 0.5f / (height + EPSF);
            float t = wp * cgv;
            float gxp = (t * gv + cds * gds) / (t + cds + EPSF);
            float cgp = (t + cds) / (wp + 1.0f);
            q = cgp;
            p = cgp * gxp;
        }
        sP[hh * 37 + ww] = p;
        sQ[hh * 37 + ww] = q;
    }
    __syncthreads();

    // Phase B: conv. thread (tx, ty) -> col tx, rows ty*4 .. ty*4+3
    const int tx = tid & 31, ty = tid >> 5;
    const int r0 = ty * 4;
    float aN[4] = {0.f, 0.f, 0.f, 0.f};
    float aD[4] = {0.f, 0.f, 0.f, 0.f};

#pragma unroll
    for (int i = 0; i < 8; i++) {
        const int sr = r0 + i;
        float pv[5], qv[5];
#pragma unroll
        for (int j = 0; j < 5; j++) {
            pv[j] = sP[sr * 37 + tx + j];
            qv[j] = sQ[sr * 37 + tx + j];
        }
#pragma unroll
        for (int k = 0; k < 4; k++) {
            const int wr = i - k;
            if (wr >= 0 && wr < 5) {
#pragma unroll
                for (int j = 0; j < 5; j++) {
                    aN[k] += sw_s[wr * 5 + j] * pv[j];
                    aD[k] += sw_s[wr * 5 + j] * qv[j];
                }
            }
        }
    }

    const float inv = s_inv;
#pragma unroll
    for (int k = 0; k < 4; k++) {
        float den = aD[k];
        float gxs = aN[k] / (den + EPSF);   // gx_s
        float qq  = den * inv;              // cgx_s
        g_pq[plane + (size_t)(h0 + r0 + k) * W + (w0 + tx)] = make_float2(qq * gxs, qq);
    }
}

// ---------------------------------------------------------------------------
// K3: 1x1 channel conv (32 -> 32) as per-pixel dual matvec, packed f32x2
// (nom and denom accumulate in one fma.rn.f32x2 since they share the weight).
// ---------------------------------------------------------------------------
__global__ __launch_bounds__(256) void k3_chconv(const float* __restrict__ bias,
                                                 float* __restrict__ out) {
    __shared__ unsigned long long cw2[O * C];
    const int tid = threadIdx.x;
    for (int i = tid; i < O * C; i += 256) {
        float w = g_cw[i];
        unsigned long long v;
        asm("mov.b64 %0, {%1, %2};" : "=l"(v) : "f"(w), "f"(w));
        cw2[i] = v;
    }
    __syncthreads();

    const int gid = blockIdx.x * 256 + tid;   // 0 .. B*HW-1
    const int b   = gid >> 16;                // HW = 65536
    const int pix = gid & (HW - 1);
    const size_t base = (size_t)b * C * HW + pix;

    unsigned long long acc[O];
#pragma unroll
    for (int o = 0; o < O; o++) acc[o] = 0ULL;

#pragma unroll 4
    for (int c = 0; c < C; c++) {
        float2 pq = g_pq[base + (size_t)c * HW];
        unsigned long long a;
        asm("mov.b64 %0, {%1, %2};" : "=l"(a) : "f"(pq.x), "f"(pq.y));
#pragma unroll
        for (int o = 0; o < O; o++) {
            asm("fma.rn.f32x2 %0, %1, %2, %0;"
                : "+l"(acc[o])
                : "l"(a), "l"(cw2[o * C + c]));
        }
    }

    const float invScw = g_invScw;
    const size_t outbase = (size_t)b * O * HW + pix;
#pragma unroll
    for (int o = 0; o < O; o++) {
        float n, dn;
        asm("mov.b64 {%0, %1}, %2;" : "=f"(n), "=f"(dn) : "l"(acc[o]));
        out[outbase + (size_t)o * HW]        = n / (dn + EPSF) + bias[o]; // gx_out
        out[NTOT + outbase + (size_t)o * HW] = dn * invScw;               // cgx_out
    }
}

// ---------------------------------------------------------------------------
extern "C" void kernel_launch(void* const* d_in, const int* in_sizes, int n_in,
                              void* d_out, int out_size) {
    const float* d     = (const float*)d_in[0];
    const float* cd    = (const float*)d_in[1];
    const float* gx    = (const float*)d_in[2];
    const float* cgx   = (const float*)d_in[3];
    const float* wprop = (const float*)d_in[4];
    const float* sw    = (const float*)d_in[5];
    const float* cw    = (const float*)d_in[6];
    const float* bias  = (const float*)d_in[7];
    float* out = (float*)d_out;

    k0_weights<<<1, 256>>>(sw, cw);

    dim3 g12(64, C, B);  // 8x8 tiles of 32x32, per (c, b)
    k12_prop_dwconv<<<g12, 256>>>(d, cd, gx, cgx, wprop, sw);

    k3_chconv<<<(B * HW) / 256, 256>>>(bias, out);
}